// round 6
// baseline (speedup 1.0000x reference)
#include <cuda_runtime.h>

// Problem constants (from reference: B=1024, S=200, Q=512)
#define PB 1024
#define PS 200
#define PQ 512
#define ROWS (PB * (PS - 1))          // 203,776 = 64 * 3184 (exact grid)
#define WARPS_PER_BLOCK 8
#define THREADS (WARPS_PER_BLOCK * 32)
#define RPW 8                         // rows processed concurrently per warp
#define NCHUNK 8                      // 8 chunks x 512B per 4KB row

__global__ void init_out_kernel(float* out) {
    if (threadIdx.x == 0) out[0] = 0.0f;
}

// Each warp owns 8 consecutive (b, s1) rows, scanned concurrently in 512B
// chunks with per-row early exit (expected read fraction 0.5125). The one-hot
// index test is arithmetic (values are exactly 0/1):
//   s = v.x*(e+1) + v.y*(e+2) + v.z*(e+3) + v.w*(e+4)
// In the found round exactly one lane has s != 0 and s == idx+1; that lane
// routes it through shared memory (no reduction chains). One __reduce_or_sync
// per round maintains the warp-uniform done mask.
__global__ __launch_bounds__(THREADS, 5)
void loss_kernel(const float* __restrict__ pred,
                 const float* __restrict__ batch,
                 float* __restrict__ out)
{
    __shared__ float warpsum[WARPS_PER_BLOCK];
    __shared__ int   sidx[WARPS_PER_BLOCK][RPW];

    const int lane   = threadIdx.x & 31;
    const int wlocal = threadIdx.x >> 5;
    const int wglob  = blockIdx.x * WARPS_PER_BLOCK + wlocal;
    const int rowBase = wglob * RPW;   // grid exact: rowBase+7 < ROWS always

    // 8 consecutive rows cross at most one b boundary:
    //   off4(r) = base4 + r*256 + (r >= cross ? 256 : 0)
    const int b0   = rowBase / (PS - 1);
    const int rem  = rowBase - b0 * (PS - 1);
    const unsigned base4 = (unsigned)(b0 * PS + rem + 1) * (2 * PQ / 4);
    const int cross = (PS - 1) - rem;  // rows until b increments (>= 1)

    if (lane < RPW) sidx[wlocal][lane] = 0;
    __syncwarp();

    const float4* __restrict__ batch4 = reinterpret_cast<const float4*>(batch);

    unsigned donemask = 0;

    #pragma unroll
    for (int c = 0; c < NCHUNK; c++) {
        // Issue phase: batch all loads for unfinished rows (independent).
        float4 v[RPW];
        #pragma unroll
        for (int r = 0; r < RPW; r++) {
            if (!((donemask >> r) & 1u)) {
                const unsigned o = base4 + r * 256u + ((r >= cross) ? 256u : 0u)
                                 + c * 32u + lane;
                v[r] = __ldg(batch4 + o);
            }
        }
        // Test phase: FMA index accumulation + smem routing on hit.
        unsigned newmask = 0;
        #pragma unroll
        for (int r = 0; r < RPW; r++) {
            if (!((donemask >> r) & 1u)) {
                const float e = (float)((c * 32 + lane) * 4 + 1);
                float s = v[r].x * e;
                s = fmaf(v[r].y, e + 1.0f, s);
                s = fmaf(v[r].z, e + 2.0f, s);
                s = fmaf(v[r].w, e + 3.0f, s);
                if (s != 0.0f) {                 // exactly one lane, one round
                    sidx[wlocal][r] = (int)s;    // idx+1
                    newmask |= (1u << r);
                }
            }
        }
        // Single warp-wide OR-reduce maintains the done mask.
        donemask |= __reduce_or_sync(0xffffffffu, newmask);
        if (donemask == 0xffu) break;
    }
    __syncwarp();

    // Lane r (r < RPW) handles row r's gather + logf (8 in parallel).
    float contrib = 0.0f;
    if (lane < RPW) {
        const int myidx = sidx[wlocal][lane] - 1;  // always found: >= 0
        const int row = rowBase + lane;
        const int b   = row / (PS - 1);
        const int s1  = row - b * (PS - 1) + 1;
        const int correct = (myidx < PQ) ? 1 : 0;
        const int qid     = correct ? myidx : (myidx - PQ);
        const float p = __ldg(pred + ((size_t)b * PS + (s1 - 1)) * PQ + qid);
        contrib = correct ? logf(p) : logf(1.0f - p);
    }

    // Sum lanes 0..7 into lane 0 (other lanes hold 0).
    contrib += __shfl_xor_sync(0xffffffffu, contrib, 4);
    contrib += __shfl_xor_sync(0xffffffffu, contrib, 2);
    contrib += __shfl_xor_sync(0xffffffffu, contrib, 1);

    if (lane == 0) warpsum[wlocal] = contrib;
    __syncthreads();

    if (threadIdx.x == 0) {
        float s = 0.0f;
        #pragma unroll
        for (int i = 0; i < WARPS_PER_BLOCK; i++) s += warpsum[i];
        atomicAdd(out, -s);   // loss = -sum(ll)
    }
}

extern "C" void kernel_launch(void* const* d_in, const int* in_sizes, int n_in,
                              void* d_out, int out_size)
{
    const float* pred  = (const float*)d_in[0];   // [B, S, Q] fp32
    const float* batch = (const float*)d_in[1];   // [B, S, 2Q] fp32
    float* out = (float*)d_out;                   // [1] fp32

    init_out_kernel<<<1, 32>>>(out);

    const int rows_per_block = WARPS_PER_BLOCK * RPW;   // 64
    const int blocks = ROWS / rows_per_block;           // 3184 (exact)
    loss_kernel<<<blocks, THREADS>>>(pred, batch, out);
}

// round 7
// speedup vs baseline: 1.0091x; 1.0091x over previous
#include <cuda_runtime.h>

// Problem constants (from reference: B=1024, S=200, Q=512)
#define PB 1024
#define PS 200
#define PQ 512
#define ROWS (PB * (PS - 1))          // 203,776 = 128 * 1592 (exact grid)
#define WARPS_PER_BLOCK 8
#define THREADS (WARPS_PER_BLOCK * 32)
#define RPW 16                        // rows processed concurrently per warp
#define NCHUNK 16                     // 16 chunks x 256B per 4KB row

__global__ void init_out_kernel(float* out) {
    if (threadIdx.x == 0) out[0] = 0.0f;
}

// Each warp owns 16 consecutive (b, s1) rows, scanned concurrently in 256B
// chunks (one float2 per lane per row per round) with per-row early exit:
// expected read fraction 0.48 of each 4KB row. The 16-way interleave keeps
// ~8 independent loads in flight per round even while rows drain, and the
// one-hot index test is arithmetic (batch values are exactly 0/1):
//   s = v.x*(e+1) + v.y*(e+2);  found lane stores idx+1 to smem directly.
// One __reduce_or_sync per round maintains the warp-uniform done mask.
__global__ __launch_bounds__(THREADS, 4)
void loss_kernel(const float* __restrict__ pred,
                 const float* __restrict__ batch,
                 float* __restrict__ out)
{
    __shared__ float warpsum[WARPS_PER_BLOCK];
    __shared__ int   sidx[WARPS_PER_BLOCK][RPW];

    const int lane   = threadIdx.x & 31;
    const int wlocal = threadIdx.x >> 5;
    const int wglob  = blockIdx.x * WARPS_PER_BLOCK + wlocal;
    const int rowBase = wglob * RPW;   // grid exact: rowBase+15 < ROWS always

    // 16 consecutive rows cross at most one b boundary (16 < PS-1):
    //   off2(r) = base2 + r*512 + (r >= cross ? 512 : 0)   [float2 units]
    const int b0   = rowBase / (PS - 1);
    const int rem  = rowBase - b0 * (PS - 1);
    const unsigned base2 = (unsigned)(b0 * PS + rem + 1) * (2 * PQ / 2);
    const int cross = (PS - 1) - rem;  // rows until b increments (>= 1)

    if (lane < RPW) sidx[wlocal][lane] = 0;
    __syncwarp();

    const float2* __restrict__ batch2 = reinterpret_cast<const float2*>(batch);

    unsigned donemask = 0;

    #pragma unroll
    for (int c = 0; c < NCHUNK; c++) {
        // Issue phase: batch all loads for unfinished rows (independent).
        float2 v[RPW];
        #pragma unroll
        for (int r = 0; r < RPW; r++) {
            if (!((donemask >> r) & 1u)) {
                const unsigned o = base2 + r * 512u + ((r >= cross) ? 512u : 0u)
                                 + c * 32u + lane;
                v[r] = __ldg(batch2 + o);
            }
        }
        // Test phase: FMA index + smem routing on hit.
        unsigned newmask = 0;
        #pragma unroll
        for (int r = 0; r < RPW; r++) {
            if (!((donemask >> r) & 1u)) {
                const float e = (float)((c * 32 + lane) * 2 + 1);
                float s = v[r].x * e;
                s = fmaf(v[r].y, e + 1.0f, s);
                if (s != 0.0f) {                 // exactly one lane, one round
                    sidx[wlocal][r] = (int)s;    // idx+1
                    newmask |= (1u << r);
                }
            }
        }
        donemask |= __reduce_or_sync(0xffffffffu, newmask);
        if (donemask == 0xffffu) break;
    }
    __syncwarp();

    // Lane r (r < RPW) handles row r's gather + logf (16 in parallel).
    float contrib = 0.0f;
    if (lane < RPW) {
        const int myidx = sidx[wlocal][lane] - 1;  // always found: >= 0
        const int row = rowBase + lane;
        const int b   = row / (PS - 1);
        const int s1  = row - b * (PS - 1) + 1;
        const int correct = (myidx < PQ) ? 1 : 0;
        const int qid     = correct ? myidx : (myidx - PQ);
        const float p = __ldg(pred + ((size_t)b * PS + (s1 - 1)) * PQ + qid);
        contrib = correct ? logf(p) : logf(1.0f - p);
    }

    // Sum lanes 0..15 into lane 0 (other lanes hold 0).
    contrib += __shfl_xor_sync(0xffffffffu, contrib, 8);
    contrib += __shfl_xor_sync(0xffffffffu, contrib, 4);
    contrib += __shfl_xor_sync(0xffffffffu, contrib, 2);
    contrib += __shfl_xor_sync(0xffffffffu, contrib, 1);

    if (lane == 0) warpsum[wlocal] = contrib;
    __syncthreads();

    if (threadIdx.x == 0) {
        float s = 0.0f;
        #pragma unroll
        for (int i = 0; i < WARPS_PER_BLOCK; i++) s += warpsum[i];
        atomicAdd(out, -s);   // loss = -sum(ll)
    }
}

extern "C" void kernel_launch(void* const* d_in, const int* in_sizes, int n_in,
                              void* d_out, int out_size)
{
    const float* pred  = (const float*)d_in[0];   // [B, S, Q] fp32
    const float* batch = (const float*)d_in[1];   // [B, S, 2Q] fp32
    float* out = (float*)d_out;                   // [1] fp32

    init_out_kernel<<<1, 32>>>(out);

    const int rows_per_block = WARPS_PER_BLOCK * RPW;   // 128
    const int blocks = ROWS / rows_per_block;           // 1592 (exact)
    loss_kernel<<<blocks, THREADS>>>(pred, batch, out);
}

// round 8
// speedup vs baseline: 1.0176x; 1.0084x over previous
#include <cuda_runtime.h>

// Problem constants (from reference: B=1024, S=200, Q=512)
#define PB 1024
#define PS 200
#define PQ 512
#define ROWS (PB * (PS - 1))          // 203,776 = 64 * 3184 (exact grid)
#define WARPS_PER_BLOCK 8
#define THREADS (WARPS_PER_BLOCK * 32)
#define RPW 8                         // rows processed concurrently per warp
#define NCHUNK 8                      // 8 chunks x 512B per 4KB row

__global__ void init_out_kernel(float* out) {
    if (threadIdx.x == 0) out[0] = 0.0f;
}

// Each warp owns 8 consecutive (b, s1) rows, scanned concurrently in 512B
// chunks (one uint4 per lane per row per round) with per-row early exit
// (expected read fraction 0.5125). Detection uses the bit patterns directly:
// batch values are exactly 0.0f (0x0) or 1.0f (0x3F800000), so
//   found-in-my-16B  <=>  (u.x|u.y|u.z|u.w) != 0        (3 LOP3 + ISETP)
// The (rare) finding lane recovers the exact element index with a short
// select chain and routes idx+1 through shared memory. One __reduce_or_sync
// per round maintains the warp-uniform done mask.
__global__ __launch_bounds__(THREADS)
void loss_kernel(const float* __restrict__ pred,
                 const float* __restrict__ batch,
                 float* __restrict__ out)
{
    __shared__ float warpsum[WARPS_PER_BLOCK];
    __shared__ int   sidx[WARPS_PER_BLOCK][RPW];

    const int lane   = threadIdx.x & 31;
    const int wlocal = threadIdx.x >> 5;
    const int wglob  = blockIdx.x * WARPS_PER_BLOCK + wlocal;
    const int rowBase = wglob * RPW;   // grid exact: rowBase+7 < ROWS always

    const uint4* __restrict__ batch4 = reinterpret_cast<const uint4*>(batch);

    unsigned off4[RPW];   // uint4 offset of each row's batch base
    #pragma unroll
    for (int r = 0; r < RPW; r++) {
        const int row = rowBase + r;
        const int b   = row / (PS - 1);
        const int s1  = row - b * (PS - 1) + 1;            // 1..S-1
        off4[r] = (unsigned)(b * PS + s1) * (2 * PQ / 4);  // *256
    }

    if (lane < RPW) sidx[wlocal][lane] = 0;
    __syncwarp();

    unsigned donemask = 0;

    #pragma unroll
    for (int c = 0; c < NCHUNK; c++) {
        // Issue phase: batch all loads for unfinished rows (independent).
        uint4 v[RPW];
        #pragma unroll
        for (int r = 0; r < RPW; r++)
            if (!((donemask >> r) & 1u))
                v[r] = __ldcs(batch4 + off4[r] + c * 32 + lane);

        // Test phase: integer OR detect; rare path recovers exact index.
        unsigned newmask = 0;
        #pragma unroll
        for (int r = 0; r < RPW; r++) {
            if (!((donemask >> r) & 1u)) {
                const unsigned m = v[r].x | v[r].y | v[r].z | v[r].w;
                if (m != 0u) {               // exactly one lane, one round
                    int off = 0;
                    if (v[r].y) off = 1;
                    if (v[r].z) off = 2;
                    if (v[r].w) off = 3;
                    const int e = (c * 32 + lane) * 4;
                    sidx[wlocal][r] = e + off + 1;   // idx+1
                    newmask |= (1u << r);
                }
            }
        }
        // Single warp-wide OR-reduce maintains the done mask.
        donemask |= __reduce_or_sync(0xffffffffu, newmask);
        if (donemask == 0xffu) break;
    }
    __syncwarp();

    // Lane r (r < RPW) handles row r's gather + logf (8 in parallel).
    float contrib = 0.0f;
    if (lane < RPW) {
        const int myidx = sidx[wlocal][lane] - 1;  // always found: >= 0
        const int row = rowBase + lane;
        const int b   = row / (PS - 1);
        const int s1  = row - b * (PS - 1) + 1;
        const int correct = (myidx < PQ) ? 1 : 0;
        const int qid     = correct ? myidx : (myidx - PQ);
        const float p = __ldg(pred + ((size_t)b * PS + (s1 - 1)) * PQ + qid);
        contrib = correct ? logf(p) : logf(1.0f - p);
    }

    // Sum lanes 0..7 into lane 0 (other lanes hold 0).
    contrib += __shfl_xor_sync(0xffffffffu, contrib, 4);
    contrib += __shfl_xor_sync(0xffffffffu, contrib, 2);
    contrib += __shfl_xor_sync(0xffffffffu, contrib, 1);

    if (lane == 0) warpsum[wlocal] = contrib;
    __syncthreads();

    if (threadIdx.x == 0) {
        float s = 0.0f;
        #pragma unroll
        for (int i = 0; i < WARPS_PER_BLOCK; i++) s += warpsum[i];
        atomicAdd(out, -s);   // loss = -sum(ll)
    }
}

extern "C" void kernel_launch(void* const* d_in, const int* in_sizes, int n_in,
                              void* d_out, int out_size)
{
    const float* pred  = (const float*)d_in[0];   // [B, S, Q] fp32
    const float* batch = (const float*)d_in[1];   // [B, S, 2Q] fp32
    float* out = (float*)d_out;                   // [1] fp32

    init_out_kernel<<<1, 32>>>(out);

    const int rows_per_block = WARPS_PER_BLOCK * RPW;   // 64
    const int blocks = ROWS / rows_per_block;           // 3184 (exact)
    loss_kernel<<<blocks, THREADS>>>(pred, batch, out);
}